// round 7
// baseline (speedup 1.0000x reference)
#include <cuda_runtime.h>

typedef unsigned long long u64;

#define KS    9
#define KK    81
#define MM    16
#define JJ    8
#define CINN  64
#define COUTN 64
#define HH    64
#define WW    64
#define NB    32
#define TLW   16
#define TLH   16
#define XROWS (TLH + 8)           /* 24 */
#define XCOLS (TLW + 8)           /* 24 */
#define XPIX  (XROWS * XCOLS)     /* 576 */
#define NCP   (CINN / 2)          /* 32 cin pairs */
#define NTHREADS 256
#define SM_XF2  (NCP * XPIX)       /* 18432 float2 = 147456 B */
#define SM_ACCF (COUTN * NTHREADS) /* 16384 floats =  65536 B */
#define SM_WS   2048               /* w slice: 2(r/i)*8j*2c*64cout floats = 8192 B */
#define SMEM_BYTES (SM_XF2 * 8 + SM_ACCF * 4 + KK * JJ * 8 + SM_WS * 4) /* 226368 */

// ---- packed fp32x2 helpers (sm_103a) ----
__device__ __forceinline__ u64 ffma2(u64 a, u64 b, u64 c) {
    u64 d;
    asm("fma.rn.f32x2 %0, %1, %2, %3;" : "=l"(d) : "l"(a), "l"(b), "l"(c));
    return d;
}
__device__ __forceinline__ u64 pack2(float lo, float hi) {
    u64 d;
    asm("mov.b64 %0, {%1, %2};" : "=l"(d) : "f"(lo), "f"(hi));
    return d;
}
__device__ __forceinline__ float2 unpack2(u64 d) {
    float2 r;
    asm("mov.b64 {%0, %1}, %2;" : "=f"(r.x), "=f"(r.y) : "l"(d));
    return r;
}

extern __shared__ float smem_raw[];

__global__ void __launch_bounds__(NTHREADS, 1)
bessel_conv_kernel(const float* __restrict__ x,
                   const float* __restrict__ T_real,
                   const float* __restrict__ T_imag,
                   const float* __restrict__ w_r,
                   const float* __restrict__ w_i,
                   const float* __restrict__ bias,
                   float* __restrict__ out)
{
    float2* xs2  = (float2*)smem_raw;                    // [NCP][24][24]
    float*  accs = smem_raw + SM_XF2 * 2;                // [COUT][256]
    u64*    Ts   = (u64*)(accs + SM_ACCF);               // [81][8] packed (Tr,Ti)
    float*  ws   = (float*)(Ts + KK * JJ);               // [32 seg][64 cout]

    const int tid   = threadIdx.x;
    const int tx    = tid & 15;
    const int ty    = tid >> 4;
    const int tileX = blockIdx.x;          // 0..3
    const int tileY = blockIdx.y;          // 0..3
    const int b     = blockIdx.z;          // 0..31

    const int gx = tileX * TLW + tx;
    const int gy = tileY * TLH + ty;

    // ---- w staging role: seg = (ri,jj,c), 8 threads per seg, 8 couts each ----
    const int seg   = tid >> 3;            // 0..31
    const int lane8 = tid & 7;             // 0..7
    const int w_ri  = seg >> 4;            // 0 = real, 1 = imag
    const int w_jj  = (seg >> 1) & 7;
    const int w_c   = seg & 1;
    float* ws_dst = ws + seg * 64 + lane8 * 8;   // 8 consecutive couts

    // ---------- stage x tile (+4 halo, zero padded), cin-paired float2 ----------
    {
        const int baseY = tileY * TLH - 4;
        const int baseX = tileX * TLW - 4;
        const float* xb = x + (size_t)b * CINN * HH * WW;
        for (int idx = tid; idx < SM_XF2; idx += NTHREADS) {
            int cp  = idx / XPIX;
            int rem = idx - cp * XPIX;
            int r   = rem / XCOLS;
            int c   = rem - r * XCOLS;
            int iy  = baseY + r;
            int ix  = baseX + c;
            float2 v = make_float2(0.0f, 0.0f);
            if (iy >= 0 && iy < HH && ix >= 0 && ix < WW) {
                const float* pb = xb + ((size_t)(2 * cp) * HH + iy) * WW + ix;
                v.x = pb[0];
                v.y = pb[(size_t)HH * WW];
            }
            xs2[idx] = v;
        }
        for (int idx = tid; idx < SM_ACCF; idx += NTHREADS)
            accs[idx] = 0.0f;
    }
    __syncthreads();

    const int pixoff = ty * XCOLS + tx;   // this thread's pixel base

#pragma unroll 1
    for (int m = 0; m < MM; ++m) {
        // ---- stage T[m] as packed (Tr,Ti) pairs: Ts[k*8+j] ----
        __syncthreads();   // previous m's readers of Ts / last ws readers done
        for (int idx = tid; idx < KK * JJ; idx += NTHREADS) {
            Ts[idx] = pack2(T_real[m * KK * JJ + idx],
                            T_imag[m * KK * JJ + idx]);
        }

        // this thread's w source pointer for cp=0 (advances 128 floats per cp)
        const float* w_src = (w_ri ? w_i : w_r)
                           + (((size_t)m * JJ + w_jj) * CINN + w_c) * COUTN
                           + lane8 * 8;

        u64 yr[32], yi[32];   // all 64 couts, packed 2-wide
#pragma unroll
        for (int t = 0; t < 32; ++t) { yr[t] = 0ULL; yi[t] = 0ULL; }

#pragma unroll 1
        for (int cp = 0; cp < NCP; ++cp) {
            // ---- stage w slice for this (m, cin-pair): broadcast source ----
            {
                const float4* s = (const float4*)(w_src + (size_t)cp * 2 * COUTN);
                float4 v0 = __ldg(s);
                float4 v1 = __ldg(s + 1);
                if (cp) __syncthreads();          // prior ws readers done
                ((float4*)ws_dst)[0] = v0;
                ((float4*)ws_dst)[1] = v1;
                __syncthreads();                  // ws (and Ts at cp=0) visible
            }

            // ---- Stage A: u[c][j] = sum_k (Tr,Ti)[k,j] * x(p+k) ----
            u64 u[2][8];
#pragma unroll
            for (int c = 0; c < 2; ++c)
#pragma unroll
                for (int jj = 0; jj < 8; ++jj) u[c][jj] = 0ULL;

            const float2* xp = xs2 + cp * XPIX + pixoff;

#pragma unroll 3
            for (int k1 = 0; k1 < 9; ++k1) {
#pragma unroll
                for (int k2 = 0; k2 < 9; ++k2) {
                    const int k = k1 * 9 + k2;
                    const ulonglong2* tk = (const ulonglong2*)(Ts + k * 8);
                    ulonglong2 t01 = tk[0];
                    ulonglong2 t23 = tk[1];
                    ulonglong2 t45 = tk[2];
                    ulonglong2 t67 = tk[3];
                    float2 xv = xp[k1 * XCOLS + k2];   // one LDS.64, both cins
                    u64 xd0 = pack2(xv.x, xv.x);
                    u64 xd1 = pack2(xv.y, xv.y);
                    u[0][0] = ffma2(t01.x, xd0, u[0][0]);
                    u[0][1] = ffma2(t01.y, xd0, u[0][1]);
                    u[0][2] = ffma2(t23.x, xd0, u[0][2]);
                    u[0][3] = ffma2(t23.y, xd0, u[0][3]);
                    u[0][4] = ffma2(t45.x, xd0, u[0][4]);
                    u[0][5] = ffma2(t45.y, xd0, u[0][5]);
                    u[0][6] = ffma2(t67.x, xd0, u[0][6]);
                    u[0][7] = ffma2(t67.y, xd0, u[0][7]);
                    u[1][0] = ffma2(t01.x, xd1, u[1][0]);
                    u[1][1] = ffma2(t01.y, xd1, u[1][1]);
                    u[1][2] = ffma2(t23.x, xd1, u[1][2]);
                    u[1][3] = ffma2(t23.y, xd1, u[1][3]);
                    u[1][4] = ffma2(t45.x, xd1, u[1][4]);
                    u[1][5] = ffma2(t45.y, xd1, u[1][5]);
                    u[1][6] = ffma2(t67.x, xd1, u[1][6]);
                    u[1][7] = ffma2(t67.y, xd1, u[1][7]);
                }
            }

            // ---- Stage B: y[0..63] += u * w (complex), w broadcast from smem ----
#pragma unroll
            for (int c = 0; c < 2; ++c) {
#pragma unroll
                for (int jj = 0; jj < 8; ++jj) {
                    float2 uv = unpack2(u[c][jj]);
                    u64 ur2  = pack2(uv.x, uv.x);
                    u64 ui2  = pack2(uv.y, uv.y);
                    u64 nui2 = pack2(-uv.y, -uv.y);
                    const ulonglong2* wrw =
                        (const ulonglong2*)(ws + (jj * 2 + c) * 64);
                    const ulonglong2* wiw =
                        (const ulonglong2*)(ws + (16 + jj * 2 + c) * 64);
#pragma unroll
                    for (int q = 0; q < 16; ++q) {
                        ulonglong2 a  = wrw[q];   // 4 couts of w_r
                        ulonglong2 bb = wiw[q];   // 4 couts of w_i
                        yr[2*q]   = ffma2(ur2,  a.x,  yr[2*q]);
                        yr[2*q]   = ffma2(nui2, bb.x, yr[2*q]);
                        yi[2*q]   = ffma2(ur2,  bb.x, yi[2*q]);
                        yi[2*q]   = ffma2(ui2,  a.x,  yi[2*q]);
                        yr[2*q+1] = ffma2(ur2,  a.y,  yr[2*q+1]);
                        yr[2*q+1] = ffma2(nui2, bb.y, yr[2*q+1]);
                        yi[2*q+1] = ffma2(ur2,  bb.y, yi[2*q+1]);
                        yi[2*q+1] = ffma2(ui2,  a.y,  yi[2*q+1]);
                    }
                }
            }
        }

        // ---- epilogue for this m: acc += yr^2 + yi^2 (smem, [cout][tid]) ----
#pragma unroll
        for (int t = 0; t < 32; ++t) {
            float2 r  = unpack2(yr[t]);
            float2 im = unpack2(yi[t]);
            float* a0 = accs + (2 * t) * NTHREADS + tid;
            float* a1 = accs + (2 * t + 1) * NTHREADS + tid;
            *a0 += r.x * r.x + im.x * im.x;
            *a1 += r.y * r.y + im.y * im.y;
        }
    }

    // ---- write all 64 couts ----
    {
        float* ob = out + (size_t)b * COUTN * HH * WW + gy * WW + gx;
#pragma unroll 8
        for (int c = 0; c < COUTN; ++c) {
            ob[(size_t)c * (HH * WW)] =
                accs[c * NTHREADS + tid] + __ldg(bias + c);
        }
    }
}

extern "C" void kernel_launch(void* const* d_in, const int* in_sizes, int n_in,
                              void* d_out, int out_size)
{
    (void)in_sizes; (void)n_in; (void)out_size;
    const float* x  = (const float*)d_in[0];
    const float* Tr = (const float*)d_in[1];
    const float* Ti = (const float*)d_in[2];
    const float* wr = (const float*)d_in[3];
    const float* wi = (const float*)d_in[4];
    const float* b  = (const float*)d_in[5];
    float* out = (float*)d_out;

    cudaFuncSetAttribute(bessel_conv_kernel,
                         cudaFuncAttributeMaxDynamicSharedMemorySize, SMEM_BYTES);

    dim3 grid(WW / TLW, HH / TLH, NB);   // (4, 4, 32) = 512 CTAs
    bessel_conv_kernel<<<grid, NTHREADS, SMEM_BYTES>>>(x, Tr, Ti, wr, wi, b, out);
}

// round 8
// speedup vs baseline: 1.6346x; 1.6346x over previous
#include <cuda_runtime.h>

typedef unsigned long long u64;

#define KS    9
#define KK    81
#define MM    16
#define JJ    8
#define CINN  64
#define COUTN 64
#define HH    64
#define WW    64
#define NB    32
#define TLW   16
#define TLH   16
#define XROWS (TLH + 8)           /* 24 */
#define XCOLS (TLW + 8)           /* 24 */
#define XPIX  (XROWS * XCOLS)     /* 576 */
#define NCP   (CINN / 2)          /* 32 cin pairs */
#define NTHREADS 256
#define SM_XF2  (NCP * XPIX)       /* 18432 float2 = 147456 B */
#define SM_ACCF (COUTN * NTHREADS) /* 16384 floats =  65536 B */
#define SM_WS   2048               /* w slice: 2(r/i)*8j*2c*64cout floats = 8192 B */
#define SMEM_BYTES (SM_XF2 * 8 + SM_ACCF * 4 + KK * JJ * 8 + SM_WS * 4) /* 226368 */

// ---- packed fp32x2 helpers (sm_103a) ----
__device__ __forceinline__ u64 ffma2(u64 a, u64 b, u64 c) {
    u64 d;
    asm("fma.rn.f32x2 %0, %1, %2, %3;" : "=l"(d) : "l"(a), "l"(b), "l"(c));
    return d;
}
__device__ __forceinline__ u64 pack2(float lo, float hi) {
    u64 d;
    asm("mov.b64 %0, {%1, %2};" : "=l"(d) : "f"(lo), "f"(hi));
    return d;
}
__device__ __forceinline__ float2 unpack2(u64 d) {
    float2 r;
    asm("mov.b64 {%0, %1}, %2;" : "=f"(r.x), "=f"(r.y) : "l"(d));
    return r;
}

extern __shared__ float smem_raw[];

__global__ void __launch_bounds__(NTHREADS, 1)
bessel_conv_kernel(const float* __restrict__ x,
                   const float* __restrict__ T_real,
                   const float* __restrict__ T_imag,
                   const float* __restrict__ w_r,
                   const float* __restrict__ w_i,
                   const float* __restrict__ bias,
                   float* __restrict__ out)
{
    float2* xs2  = (float2*)smem_raw;                    // [NCP][24][24]
    float*  accs = smem_raw + SM_XF2 * 2;                // [COUT][256]
    u64*    Ts   = (u64*)(accs + SM_ACCF);               // [81][8] packed (Tr,Ti)
    float*  ws   = (float*)(Ts + KK * JJ);               // [32 seg][64 cout]

    const int tid   = threadIdx.x;
    const int tx    = tid & 15;
    const int ty    = tid >> 4;
    const int tileX = blockIdx.x;          // 0..3
    const int tileY = blockIdx.y;          // 0..3
    const int b     = blockIdx.z;          // 0..31

    const int gx = tileX * TLW + tx;
    const int gy = tileY * TLH + ty;

    // ---- w staging role: seg = (ri,jj,c), 8 threads per seg, 8 couts each ----
    const int seg   = tid >> 3;            // 0..31
    const int lane8 = tid & 7;             // 0..7
    const int w_ri  = seg >> 4;            // 0 = real, 1 = imag
    const int w_jj  = (seg >> 1) & 7;
    const int w_c   = seg & 1;
    float* ws_dst = ws + seg * 64 + lane8 * 8;   // 8 consecutive couts

    // ---------- stage x tile (+4 halo, zero padded), cin-paired float2 ----------
    {
        const int baseY = tileY * TLH - 4;
        const int baseX = tileX * TLW - 4;
        const float* xb = x + (size_t)b * CINN * HH * WW;
        for (int idx = tid; idx < SM_XF2; idx += NTHREADS) {
            int cp  = idx / XPIX;
            int rem = idx - cp * XPIX;
            int r   = rem / XCOLS;
            int c   = rem - r * XCOLS;
            int iy  = baseY + r;
            int ix  = baseX + c;
            float2 v = make_float2(0.0f, 0.0f);
            if (iy >= 0 && iy < HH && ix >= 0 && ix < WW) {
                const float* pb = xb + ((size_t)(2 * cp) * HH + iy) * WW + ix;
                v.x = pb[0];
                v.y = pb[(size_t)HH * WW];
            }
            xs2[idx] = v;
        }
        for (int idx = tid; idx < SM_ACCF; idx += NTHREADS)
            accs[idx] = 0.0f;
    }
    __syncthreads();

    const int pixoff = ty * XCOLS + tx;   // this thread's pixel base

#pragma unroll 1
    for (int m = 0; m < MM; ++m) {
        // ---- stage T[m] as packed (Tr,Ti) pairs: Ts[k*8+j] ----
        __syncthreads();   // previous m's readers of Ts / last ws readers done
        for (int idx = tid; idx < KK * JJ; idx += NTHREADS) {
            Ts[idx] = pack2(T_real[m * KK * JJ + idx],
                            T_imag[m * KK * JJ + idx]);
        }

        // this thread's w source pointer for cp=0 (advances 128 floats per cp)
        const float* w_src = (w_ri ? w_i : w_r)
                           + (((size_t)m * JJ + w_jj) * CINN + w_c) * COUTN
                           + lane8 * 8;

        u64 yr[32], yi[32];   // all 64 couts, packed 2-wide
#pragma unroll
        for (int t = 0; t < 32; ++t) { yr[t] = 0ULL; yi[t] = 0ULL; }

#pragma unroll 1
        for (int cp = 0; cp < NCP; ++cp) {
            // ---- stage w slice for this (m, cin-pair): broadcast source ----
            {
                const float4* s = (const float4*)(w_src + (size_t)cp * 2 * COUTN);
                float4 v0 = __ldg(s);
                float4 v1 = __ldg(s + 1);
                if (cp) __syncthreads();          // prior ws readers done
                ((float4*)ws_dst)[0] = v0;
                ((float4*)ws_dst)[1] = v1;
                __syncthreads();                  // ws (and Ts at cp=0) visible
            }

            // ---- Stage A: u[c][j] = sum_k (Tr,Ti)[k,j] * x(p+k) ----
            u64 u[2][8];
#pragma unroll
            for (int c = 0; c < 2; ++c)
#pragma unroll
                for (int jj = 0; jj < 8; ++jj) u[c][jj] = 0ULL;

            const float2* xp = xs2 + cp * XPIX + pixoff;

#pragma unroll 3
            for (int k1 = 0; k1 < 9; ++k1) {
#pragma unroll
                for (int k2 = 0; k2 < 9; ++k2) {
                    const int k = k1 * 9 + k2;
                    const ulonglong2* tk = (const ulonglong2*)(Ts + k * 8);
                    ulonglong2 t01 = tk[0];
                    ulonglong2 t23 = tk[1];
                    ulonglong2 t45 = tk[2];
                    ulonglong2 t67 = tk[3];
                    float2 xv = xp[k1 * XCOLS + k2];   // one LDS.64, both cins
                    u64 xd0 = pack2(xv.x, xv.x);
                    u64 xd1 = pack2(xv.y, xv.y);
                    u[0][0] = ffma2(t01.x, xd0, u[0][0]);
                    u[0][1] = ffma2(t01.y, xd0, u[0][1]);
                    u[0][2] = ffma2(t23.x, xd0, u[0][2]);
                    u[0][3] = ffma2(t23.y, xd0, u[0][3]);
                    u[0][4] = ffma2(t45.x, xd0, u[0][4]);
                    u[0][5] = ffma2(t45.y, xd0, u[0][5]);
                    u[0][6] = ffma2(t67.x, xd0, u[0][6]);
                    u[0][7] = ffma2(t67.y, xd0, u[0][7]);
                    u[1][0] = ffma2(t01.x, xd1, u[1][0]);
                    u[1][1] = ffma2(t01.y, xd1, u[1][1]);
                    u[1][2] = ffma2(t23.x, xd1, u[1][2]);
                    u[1][3] = ffma2(t23.y, xd1, u[1][3]);
                    u[1][4] = ffma2(t45.x, xd1, u[1][4]);
                    u[1][5] = ffma2(t45.y, xd1, u[1][5]);
                    u[1][6] = ffma2(t67.x, xd1, u[1][6]);
                    u[1][7] = ffma2(t67.y, xd1, u[1][7]);
                }
            }

            // ---- Stage B: y[0..63] += u * w (complex), w broadcast from smem ----
#pragma unroll
            for (int c = 0; c < 2; ++c) {
#pragma unroll
                for (int jj = 0; jj < 8; ++jj) {
                    float2 uv = unpack2(u[c][jj]);
                    u64 ur2  = pack2(uv.x, uv.x);
                    u64 ui2  = pack2(uv.y, uv.y);
                    u64 nui2 = pack2(-uv.y, -uv.y);
                    const ulonglong2* wrw =
                        (const ulonglong2*)(ws + (jj * 2 + c) * 64);
                    const ulonglong2* wiw =
                        (const ulonglong2*)(ws + (16 + jj * 2 + c) * 64);
#pragma unroll
                    for (int q = 0; q < 16; ++q) {
                        ulonglong2 a  = wrw[q];   // 4 couts of w_r
                        ulonglong2 bb = wiw[q];   // 4 couts of w_i
                        yr[2*q]   = ffma2(ur2,  a.x,  yr[2*q]);
                        yr[2*q]   = ffma2(nui2, bb.x, yr[2*q]);
                        yi[2*q]   = ffma2(ur2,  bb.x, yi[2*q]);
                        yi[2*q]   = ffma2(ui2,  a.x,  yi[2*q]);
                        yr[2*q+1] = ffma2(ur2,  a.y,  yr[2*q+1]);
                        yr[2*q+1] = ffma2(nui2, bb.y, yr[2*q+1]);
                        yi[2*q+1] = ffma2(ur2,  bb.y, yi[2*q+1]);
                        yi[2*q+1] = ffma2(ui2,  a.y,  yi[2*q+1]);
                    }
                }
            }
        }

        // ---- epilogue for this m: acc += yr^2 + yi^2 (smem, [cout][tid]) ----
#pragma unroll
        for (int t = 0; t < 32; ++t) {
            float2 r  = unpack2(yr[t]);
            float2 im = unpack2(yi[t]);
            float* a0 = accs + (2 * t) * NTHREADS + tid;
            float* a1 = accs + (2 * t + 1) * NTHREADS + tid;
            *a0 += r.x * r.x + im.x * im.x;
            *a1 += r.y * r.y + im.y * im.y;
        }
    }

    // ---- write all 64 couts ----
    {
        float* ob = out + (size_t)b * COUTN * HH * WW + gy * WW + gx;
#pragma unroll 8
        for (int c = 0; c < COUTN; ++c) {
            ob[(size_t)c * (HH * WW)] =
                accs[c * NTHREADS + tid] + __ldg(bias + c);
        }
    }
}

extern "C" void kernel_launch(void* const* d_in, const int* in_sizes, int n_in,
                              void* d_out, int out_size)
{
    (void)in_sizes; (void)n_in; (void)out_size;
    const float* x  = (const float*)d_in[0];
    const float* Tr = (const float*)d_in[1];
    const float* Ti = (const float*)d_in[2];
    const float* wr = (const float*)d_in[3];
    const float* wi = (const float*)d_in[4];
    const float* b  = (const float*)d_in[5];
    float* out = (float*)d_out;

    cudaFuncSetAttribute(bessel_conv_kernel,
                         cudaFuncAttributeMaxDynamicSharedMemorySize, SMEM_BYTES);

    dim3 grid(WW / TLW, HH / TLH, NB);   // (4, 4, 32) = 512 CTAs
    bessel_conv_kernel<<<grid, NTHREADS, SMEM_BYTES>>>(x, Tr, Ti, wr, wi, b, out);
}

// round 9
// speedup vs baseline: 1.6390x; 1.0027x over previous
#include <cuda_runtime.h>

typedef unsigned long long u64;

#define KK    81
#define MM    16
#define JJ    8
#define CINN  64
#define COUTN 64
#define HH    64
#define WW    64
#define NB    32
#define TLW   16
#define TLH   16
#define XROWS (TLH + 8)           /* 24 */
#define XCOLS (TLW + 8)           /* 24 */
#define XPIX  (XROWS * XCOLS)     /* 576 */
#define NCP   (CINN / 2)          /* 32 cin pairs */
#define NCQ   (CINN / 4)          /* 16 4-cin blocks */
#define NTHREADS 256
#define SM_XF2  (NCP * XPIX)       /* 18432 float2 = 147456 B */
#define SM_WSF  4096               /* w slice: 2(r/i)*8j*4c*64cout floats = 16384 B */
#define SMEM_BYTES (SM_XF2 * 8 + KK * JJ * 8 + SM_WSF * 4) /* 169024 */

// ---- packed fp32x2 helpers (sm_103a) ----
__device__ __forceinline__ u64 ffma2(u64 a, u64 b, u64 c) {
    u64 d;
    asm("fma.rn.f32x2 %0, %1, %2, %3;" : "=l"(d) : "l"(a), "l"(b), "l"(c));
    return d;
}
__device__ __forceinline__ u64 pack2(float lo, float hi) {
    u64 d;
    asm("mov.b64 %0, {%1, %2};" : "=l"(d) : "f"(lo), "f"(hi));
    return d;
}
__device__ __forceinline__ float2 unpack2(u64 d) {
    float2 r;
    asm("mov.b64 {%0, %1}, %2;" : "=f"(r.x), "=f"(r.y) : "l"(d));
    return r;
}

extern __shared__ float smem_raw[];

__global__ void __launch_bounds__(NTHREADS, 1)
bessel_conv_kernel(const float* __restrict__ x,
                   const float* __restrict__ T_real,
                   const float* __restrict__ T_imag,
                   const float* __restrict__ w_r,
                   const float* __restrict__ w_i,
                   const float* __restrict__ bias,
                   float* __restrict__ out)
{
    float2* xs2 = (float2*)smem_raw;                 // [NCP][24][24]
    u64*    Ts  = (u64*)(smem_raw + SM_XF2 * 2);     // [81][8] packed (Tr,Ti)
    float*  ws  = (float*)(Ts + KK * JJ);            // [64 seg][64 cout]

    const int tid   = threadIdx.x;
    const int tx    = tid & 15;
    const int ty    = tid >> 4;
    const int tileX = blockIdx.x;          // 0..3
    const int tileY = blockIdx.y;          // 0..3
    const int b     = blockIdx.z;          // 0..31

    const int gx = tileX * TLW + tx;
    const int gy = tileY * TLH + ty;

    // ---- w staging role: seg = (ri,jj,c) of 64, 4 threads/seg, 16 couts each ----
    const int seg   = tid >> 2;            // 0..63
    const int lane4 = tid & 3;             // 0..3
    const int w_ri  = seg >> 5;            // 0 = real, 1 = imag
    const int w_jj  = (seg >> 2) & 7;
    const int w_c   = seg & 3;
    float* ws_dst = ws + seg * 64 + lane4 * 16;
    const float* wbase0 = w_ri ? w_i : w_r;

    // ---------- stage x tile (+4 halo, zero padded), cin-paired float2 ----------
    {
        const int baseY = tileY * TLH - 4;
        const int baseX = tileX * TLW - 4;
        const float* xb = x + (size_t)b * CINN * HH * WW;
        for (int idx = tid; idx < SM_XF2; idx += NTHREADS) {
            int cp  = idx / XPIX;
            int rem = idx - cp * XPIX;
            int r   = rem / XCOLS;
            int c   = rem - r * XCOLS;
            int iy  = baseY + r;
            int ix  = baseX + c;
            float2 v = make_float2(0.0f, 0.0f);
            if (iy >= 0 && iy < HH && ix >= 0 && ix < WW) {
                const float* pb = xb + ((size_t)(2 * cp) * HH + iy) * WW + ix;
                v.x = pb[0];
                v.y = pb[(size_t)HH * WW];
            }
            xs2[idx] = v;
        }
    }
    __syncthreads();

    const int pixoff = ty * XCOLS + tx;   // this thread's pixel base
    float* ob = out + (size_t)b * COUTN * (HH * WW) + gy * WW + gx;

#pragma unroll 1
    for (int m = 0; m < MM; ++m) {
        __syncthreads();   // previous m's readers of Ts/ws are done
        // ---- stage T[m] as packed (Tr,Ti) pairs: Ts[k*8+j] ----
        for (int idx = tid; idx < KK * JJ; idx += NTHREADS) {
            Ts[idx] = pack2(T_real[m * KK * JJ + idx],
                            T_imag[m * KK * JJ + idx]);
        }

        // this thread's w source for cq=0 (advances 256 floats per cq)
        const float* w_src = wbase0
                           + (((size_t)m * JJ + w_jj) * CINN + w_c) * COUTN
                           + lane4 * 16;
        float4 wv0 = __ldg((const float4*)w_src);
        float4 wv1 = __ldg((const float4*)w_src + 1);
        float4 wv2 = __ldg((const float4*)w_src + 2);
        float4 wv3 = __ldg((const float4*)w_src + 3);

        u64 yr[32], yi[32];   // all 64 couts, packed 2-wide
#pragma unroll
        for (int t = 0; t < 32; ++t) { yr[t] = 0ULL; yi[t] = 0ULL; }

#pragma unroll 1
        for (int cq = 0; cq < NCQ; ++cq) {
            // ---- commit staged w regs to smem ----
            __syncthreads();          // prior ws readers done; Ts visible at cq=0
            ((float4*)ws_dst)[0] = wv0;
            ((float4*)ws_dst)[1] = wv1;
            ((float4*)ws_dst)[2] = wv2;
            ((float4*)ws_dst)[3] = wv3;
            __syncthreads();          // ws visible
            if (cq < NCQ - 1) {       // prefetch next slice (latency hidden)
                const float4* s =
                    (const float4*)(w_src + (size_t)(cq + 1) * 4 * COUTN);
                wv0 = __ldg(s);
                wv1 = __ldg(s + 1);
                wv2 = __ldg(s + 2);
                wv3 = __ldg(s + 3);
            }

            // ---- Stage A: u[c][j], 4 cins, T tap loaded once ----
            u64 u[4][8];
#pragma unroll
            for (int c = 0; c < 4; ++c)
#pragma unroll
                for (int jj = 0; jj < 8; ++jj) u[c][jj] = 0ULL;

            const float2* xp0 = xs2 + (2 * cq) * XPIX + pixoff;
            const float2* xp1 = xp0 + XPIX;

#pragma unroll 3
            for (int k1 = 0; k1 < 9; ++k1) {
#pragma unroll
                for (int k2 = 0; k2 < 9; ++k2) {
                    const int k = k1 * 9 + k2;
                    float2 xv01 = xp0[k1 * XCOLS + k2];
                    float2 xv23 = xp1[k1 * XCOLS + k2];
                    u64 xd0 = pack2(xv01.x, xv01.x);
                    u64 xd1 = pack2(xv01.y, xv01.y);
                    u64 xd2 = pack2(xv23.x, xv23.x);
                    u64 xd3 = pack2(xv23.y, xv23.y);
                    const ulonglong2* tk = (const ulonglong2*)(Ts + k * 8);
#pragma unroll
                    for (int jq = 0; jq < 4; ++jq) {
                        ulonglong2 t = tk[jq];   // packed T for j=2jq, 2jq+1
                        u[0][2*jq]   = ffma2(t.x, xd0, u[0][2*jq]);
                        u[0][2*jq+1] = ffma2(t.y, xd0, u[0][2*jq+1]);
                        u[1][2*jq]   = ffma2(t.x, xd1, u[1][2*jq]);
                        u[1][2*jq+1] = ffma2(t.y, xd1, u[1][2*jq+1]);
                        u[2][2*jq]   = ffma2(t.x, xd2, u[2][2*jq]);
                        u[2][2*jq+1] = ffma2(t.y, xd2, u[2][2*jq+1]);
                        u[3][2*jq]   = ffma2(t.x, xd3, u[3][2*jq]);
                        u[3][2*jq+1] = ffma2(t.y, xd3, u[3][2*jq+1]);
                    }
                }
            }

            // ---- Stage B: y[0..63] += u * w (complex), w broadcast from smem ----
#pragma unroll
            for (int c = 0; c < 4; ++c) {
#pragma unroll
                for (int jj = 0; jj < 8; ++jj) {
                    float2 uv = unpack2(u[c][jj]);
                    u64 ur2  = pack2(uv.x, uv.x);
                    u64 ui2  = pack2(uv.y, uv.y);
                    u64 nui2 = pack2(-uv.y, -uv.y);
                    const ulonglong2* wrw =
                        (const ulonglong2*)(ws + (jj * 4 + c) * 64);
                    const ulonglong2* wiw =
                        (const ulonglong2*)(ws + (32 + jj * 4 + c) * 64);
#pragma unroll
                    for (int q = 0; q < 16; ++q) {
                        ulonglong2 a  = wrw[q];   // 4 couts of w_r
                        ulonglong2 bb = wiw[q];   // 4 couts of w_i
                        yr[2*q]   = ffma2(ur2,  a.x,  yr[2*q]);
                        yr[2*q]   = ffma2(nui2, bb.x, yr[2*q]);
                        yi[2*q]   = ffma2(ur2,  bb.x, yi[2*q]);
                        yi[2*q]   = ffma2(ui2,  a.x,  yi[2*q]);
                        yr[2*q+1] = ffma2(ur2,  a.y,  yr[2*q+1]);
                        yr[2*q+1] = ffma2(nui2, bb.y, yr[2*q+1]);
                        yi[2*q+1] = ffma2(ur2,  bb.y, yi[2*q+1]);
                        yi[2*q+1] = ffma2(ui2,  a.y,  yi[2*q+1]);
                    }
                }
            }
        }

        // ---- epilogue: out RMW. m=0 initializes (poison never read) ----
        if (m == 0) {
#pragma unroll
            for (int t = 0; t < 32; ++t) {
                float2 r  = unpack2(yr[t]);
                float2 im = unpack2(yi[t]);
                ob[(size_t)(2*t)     * (HH*WW)] =
                    r.x * r.x + im.x * im.x + __ldg(bias + 2*t);
                ob[(size_t)(2*t + 1) * (HH*WW)] =
                    r.y * r.y + im.y * im.y + __ldg(bias + 2*t + 1);
            }
        } else {
#pragma unroll
            for (int t = 0; t < 32; ++t) {
                float2 r  = unpack2(yr[t]);
                float2 im = unpack2(yi[t]);
                float p0 = ob[(size_t)(2*t)     * (HH*WW)];
                float p1 = ob[(size_t)(2*t + 1) * (HH*WW)];
                ob[(size_t)(2*t)     * (HH*WW)] = p0 + r.x * r.x + im.x * im.x;
                ob[(size_t)(2*t + 1) * (HH*WW)] = p1 + r.y * r.y + im.y * im.y;
            }
        }
    }
}

extern "C" void kernel_launch(void* const* d_in, const int* in_sizes, int n_in,
                              void* d_out, int out_size)
{
    (void)in_sizes; (void)n_in; (void)out_size;
    const float* x  = (const float*)d_in[0];
    const float* Tr = (const float*)d_in[1];
    const float* Ti = (const float*)d_in[2];
    const float* wr = (const float*)d_in[3];
    const float* wi = (const float*)d_in[4];
    const float* b  = (const float*)d_in[5];
    float* out = (float*)d_out;

    cudaFuncSetAttribute(bessel_conv_kernel,
                         cudaFuncAttributeMaxDynamicSharedMemorySize, SMEM_BYTES);

    dim3 grid(WW / TLW, HH / TLH, NB);   // (4, 4, 32) = 512 CTAs
    bessel_conv_kernel<<<grid, NTHREADS, SMEM_BYTES>>>(x, Tr, Ti, wr, wi, b, out);
}

// round 10
// speedup vs baseline: 1.6394x; 1.0002x over previous
#include <cuda_runtime.h>

typedef unsigned long long u64;

#define KK    81
#define MM    16
#define JJ    8
#define CINN  64
#define COUTN 64
#define HH    64
#define WW    64
#define NB    32
#define TLW   16
#define TLH   16
#define XROWS (TLH + 8)           /* 24 */
#define XCOLS (TLW + 8)           /* 24 */
#define XPIX  (XROWS * XCOLS)     /* 576 */
#define NCP   (CINN / 2)          /* 32 cin pairs */
#define NCQ   (CINN / 4)          /* 16 4-cin blocks */
#define NTHREADS 256
#define SM_XF2  (NCP * XPIX)       /* 18432 float2 = 147456 B */
#define SM_WSF  4096               /* w slice: 2(r/i)*8j*4c*64cout floats = 16384 B */
#define SMEM_BYTES (SM_XF2 * 8 + KK * JJ * 8 + SM_WSF * 4) /* 169024 */

// ---- packed fp32x2 helpers (sm_103a) ----
__device__ __forceinline__ u64 ffma2(u64 a, u64 b, u64 c) {
    u64 d;
    asm("fma.rn.f32x2 %0, %1, %2, %3;" : "=l"(d) : "l"(a), "l"(b), "l"(c));
    return d;
}
__device__ __forceinline__ u64 pack2(float lo, float hi) {
    u64 d;
    asm("mov.b64 %0, {%1, %2};" : "=l"(d) : "f"(lo), "f"(hi));
    return d;
}
__device__ __forceinline__ float2 unpack2(u64 d) {
    float2 r;
    asm("mov.b64 {%0, %1}, %2;" : "=f"(r.x), "=f"(r.y) : "l"(d));
    return r;
}

extern __shared__ float smem_raw[];

__global__ void __launch_bounds__(NTHREADS, 1)
bessel_conv_kernel(const float* __restrict__ x,
                   const float* __restrict__ T_real,
                   const float* __restrict__ T_imag,
                   const float* __restrict__ w_r,
                   const float* __restrict__ w_i,
                   const float* __restrict__ bias,
                   float* __restrict__ out)
{
    float2* xs2 = (float2*)smem_raw;                 // [NCP][24][24]
    u64*    Ts  = (u64*)(smem_raw + SM_XF2 * 2);     // [81][8] packed (Tr,Ti)
    float*  ws  = (float*)(Ts + KK * JJ);            // [64 seg][64 cout]

    const int tid   = threadIdx.x;
    const int tx    = tid & 15;
    const int ty    = tid >> 4;
    const int tileX = blockIdx.x;          // 0..3
    const int tileY = blockIdx.y;          // 0..3
    const int b     = blockIdx.z;          // 0..31

    const int gx = tileX * TLW + tx;
    const int gy = tileY * TLH + ty;

    // ---- w staging role: seg = (ri,jj,c) of 64, 4 threads/seg, 16 couts each ----
    const int seg   = tid >> 2;            // 0..63
    const int lane4 = tid & 3;             // 0..3
    const int w_ri  = seg >> 5;            // 0 = real, 1 = imag
    const int w_jj  = (seg >> 2) & 7;
    const int w_c   = seg & 3;
    float* ws_dst = ws + seg * 64 + lane4 * 16;
    const float* wbase0 = w_ri ? w_i : w_r;

    // ---------- stage x tile (+4 halo, zero padded), cin-paired float2 ----------
    {
        const int baseY = tileY * TLH - 4;
        const int baseX = tileX * TLW - 4;
        const float* xb = x + (size_t)b * CINN * HH * WW;
        for (int idx = tid; idx < SM_XF2; idx += NTHREADS) {
            int cp  = idx / XPIX;
            int rem = idx - cp * XPIX;
            int r   = rem / XCOLS;
            int c   = rem - r * XCOLS;
            int iy  = baseY + r;
            int ix  = baseX + c;
            float2 v = make_float2(0.0f, 0.0f);
            if (iy >= 0 && iy < HH && ix >= 0 && ix < WW) {
                const float* pb = xb + ((size_t)(2 * cp) * HH + iy) * WW + ix;
                v.x = pb[0];
                v.y = pb[(size_t)HH * WW];
            }
            xs2[idx] = v;
        }
    }
    __syncthreads();

    const int pixoff = ty * XCOLS + tx;   // this thread's pixel base
    float* ob = out + (size_t)b * COUTN * (HH * WW) + gy * WW + gx;

#pragma unroll 1
    for (int m = 0; m < MM; ++m) {
        __syncthreads();   // previous m's readers of Ts/ws are done
        // ---- stage T[m] as packed (Tr,Ti) pairs: Ts[k*8+j] ----
        for (int idx = tid; idx < KK * JJ; idx += NTHREADS) {
            Ts[idx] = pack2(T_real[m * KK * JJ + idx],
                            T_imag[m * KK * JJ + idx]);
        }

        // this thread's w source for cq=0 (advances 256 floats per cq)
        const float* w_src = wbase0
                           + (((size_t)m * JJ + w_jj) * CINN + w_c) * COUTN
                           + lane4 * 16;
        float4 wv0 = __ldg((const float4*)w_src);
        float4 wv1 = __ldg((const float4*)w_src + 1);
        float4 wv2 = __ldg((const float4*)w_src + 2);
        float4 wv3 = __ldg((const float4*)w_src + 3);

        u64 yr[32], yi[32];   // all 64 couts, packed 2-wide
#pragma unroll
        for (int t = 0; t < 32; ++t) { yr[t] = 0ULL; yi[t] = 0ULL; }

#pragma unroll 1
        for (int cq = 0; cq < NCQ; ++cq) {
            // ---- commit staged w regs to smem ----
            __syncthreads();          // prior ws readers done; Ts visible at cq=0
            ((float4*)ws_dst)[0] = wv0;
            ((float4*)ws_dst)[1] = wv1;
            ((float4*)ws_dst)[2] = wv2;
            ((float4*)ws_dst)[3] = wv3;
            __syncthreads();          // ws visible
            if (cq < NCQ - 1) {       // prefetch next slice (latency hidden)
                const float4* s =
                    (const float4*)(w_src + (size_t)(cq + 1) * 4 * COUTN);
                wv0 = __ldg(s);
                wv1 = __ldg(s + 1);
                wv2 = __ldg(s + 2);
                wv3 = __ldg(s + 3);
            }

            // ---- Stage A: u[c][j], 4 cins, T tap loaded once ----
            u64 u[4][8];
#pragma unroll
            for (int c = 0; c < 4; ++c)
#pragma unroll
                for (int jj = 0; jj < 8; ++jj) u[c][jj] = 0ULL;

            const float2* xp0 = xs2 + (2 * cq) * XPIX + pixoff;
            const float2* xp1 = xp0 + XPIX;

#pragma unroll 3
            for (int k1 = 0; k1 < 9; ++k1) {
#pragma unroll
                for (int k2 = 0; k2 < 9; ++k2) {
                    const int k = k1 * 9 + k2;
                    float2 xv01 = xp0[k1 * XCOLS + k2];
                    float2 xv23 = xp1[k1 * XCOLS + k2];
                    u64 xd0 = pack2(xv01.x, xv01.x);
                    u64 xd1 = pack2(xv01.y, xv01.y);
                    u64 xd2 = pack2(xv23.x, xv23.x);
                    u64 xd3 = pack2(xv23.y, xv23.y);
                    const ulonglong2* tk = (const ulonglong2*)(Ts + k * 8);
#pragma unroll
                    for (int jq = 0; jq < 4; ++jq) {
                        ulonglong2 t = tk[jq];   // packed T for j=2jq, 2jq+1
                        u[0][2*jq]   = ffma2(t.x, xd0, u[0][2*jq]);
                        u[0][2*jq+1] = ffma2(t.y, xd0, u[0][2*jq+1]);
                        u[1][2*jq]   = ffma2(t.x, xd1, u[1][2*jq]);
                        u[1][2*jq+1] = ffma2(t.y, xd1, u[1][2*jq+1]);
                        u[2][2*jq]   = ffma2(t.x, xd2, u[2][2*jq]);
                        u[2][2*jq+1] = ffma2(t.y, xd2, u[2][2*jq+1]);
                        u[3][2*jq]   = ffma2(t.x, xd3, u[3][2*jq]);
                        u[3][2*jq+1] = ffma2(t.y, xd3, u[3][2*jq+1]);
                    }
                }
            }

            // ---- Stage B: y[0..63] += u * w (complex), w broadcast from smem ----
#pragma unroll
            for (int c = 0; c < 4; ++c) {
#pragma unroll
                for (int jj = 0; jj < 8; ++jj) {
                    float2 uv = unpack2(u[c][jj]);
                    u64 ur2  = pack2(uv.x, uv.x);
                    u64 ui2  = pack2(uv.y, uv.y);
                    u64 nui2 = pack2(-uv.y, -uv.y);
                    const ulonglong2* wrw =
                        (const ulonglong2*)(ws + (jj * 4 + c) * 64);
                    const ulonglong2* wiw =
                        (const ulonglong2*)(ws + (32 + jj * 4 + c) * 64);
#pragma unroll
                    for (int q = 0; q < 16; ++q) {
                        ulonglong2 a  = wrw[q];   // 4 couts of w_r
                        ulonglong2 bb = wiw[q];   // 4 couts of w_i
                        yr[2*q]   = ffma2(ur2,  a.x,  yr[2*q]);
                        yr[2*q]   = ffma2(nui2, bb.x, yr[2*q]);
                        yi[2*q]   = ffma2(ur2,  bb.x, yi[2*q]);
                        yi[2*q]   = ffma2(ui2,  a.x,  yi[2*q]);
                        yr[2*q+1] = ffma2(ur2,  a.y,  yr[2*q+1]);
                        yr[2*q+1] = ffma2(nui2, bb.y, yr[2*q+1]);
                        yi[2*q+1] = ffma2(ur2,  bb.y, yi[2*q+1]);
                        yi[2*q+1] = ffma2(ui2,  a.y,  yi[2*q+1]);
                    }
                }
            }
        }

        // ---- epilogue: out RMW. m=0 initializes (poison never read) ----
        if (m == 0) {
#pragma unroll
            for (int t = 0; t < 32; ++t) {
                float2 r  = unpack2(yr[t]);
                float2 im = unpack2(yi[t]);
                ob[(size_t)(2*t)     * (HH*WW)] =
                    r.x * r.x + im.x * im.x + __ldg(bias + 2*t);
                ob[(size_t)(2*t + 1) * (HH*WW)] =
                    r.y * r.y + im.y * im.y + __ldg(bias + 2*t + 1);
            }
        } else {
#pragma unroll
            for (int t = 0; t < 32; ++t) {
                float2 r  = unpack2(yr[t]);
                float2 im = unpack2(yi[t]);
                float p0 = ob[(size_t)(2*t)     * (HH*WW)];
                float p1 = ob[(size_t)(2*t + 1) * (HH*WW)];
                ob[(size_t)(2*t)     * (HH*WW)] = p0 + r.x * r.x + im.x * im.x;
                ob[(size_t)(2*t + 1) * (HH*WW)] = p1 + r.y * r.y + im.y * im.y;
            }
        }
    }
}

extern "C" void kernel_launch(void* const* d_in, const int* in_sizes, int n_in,
                              void* d_out, int out_size)
{
    (void)in_sizes; (void)n_in; (void)out_size;
    const float* x  = (const float*)d_in[0];
    const float* Tr = (const float*)d_in[1];
    const float* Ti = (const float*)d_in[2];
    const float* wr = (const float*)d_in[3];
    const float* wi = (const float*)d_in[4];
    const float* b  = (const float*)d_in[5];
    float* out = (float*)d_out;

    cudaFuncSetAttribute(bessel_conv_kernel,
                         cudaFuncAttributeMaxDynamicSharedMemorySize, SMEM_BYTES);

    dim3 grid(WW / TLW, HH / TLH, NB);   // (4, 4, 32) = 512 CTAs
    bessel_conv_kernel<<<grid, NTHREADS, SMEM_BYTES>>>(x, Tr, Ti, wr, wi, b, out);
}